// round 7
// baseline (speedup 1.0000x reference)
#include <cuda_runtime.h>

#define DIM   512
#define CDIM  12
#define NTOK  16384
#define CSIZE 4096
#define GRID  1024
#define BLK   256

#define OUT_OFF_IDX (NTOK * DIM)            // 8388608
#define OUT_OFF_AUX (OUT_OFF_IDX + NTOK)    // 8404992
#define LOG_EPS_NEG 11.512925464970229f     // -ln(1e-5)
#define A_MAX       20.723265837f           // ln(1e9)
#define FULL        0xffffffffu

// smem layout (floats): w_in 6144 | w_out^T 6144 | bm 512 | bp 512
#define SM_WIN  0
#define SM_WT   6144
#define SM_BM   12288
#define SM_BP   12800
#define SM_FLTS 13312
#define SM_BYTES (SM_FLTS * 4)

// ---- device scratch (no allocations allowed) ----
__device__ float g_avg[CSIZE];
__device__ float g_pse;
__device__ int   g_flag = 0;
__device__ int   g_cnt  = 0;

typedef unsigned long long u64;

__device__ __forceinline__ u64 fma2(u64 a, u64 b, u64 c) {
    u64 d; asm("fma.rn.f32x2 %0, %1, %2, %3;" : "=l"(d) : "l"(a), "l"(b), "l"(c));
    return d;
}
__device__ __forceinline__ u64 add2(u64 a, u64 b) {
    u64 d; asm("add.rn.f32x2 %0, %1, %2;" : "=l"(d) : "l"(a), "l"(b));
    return d;
}
__device__ __forceinline__ u64 pack2(float lo, float hi) {
    u64 d; asm("mov.b64 %0, {%1, %2};" : "=l"(d) : "f"(lo), "f"(hi));
    return d;
}
__device__ __forceinline__ float fold2(u64 v) {   // lo + hi
    float lo, hi; asm("mov.b64 {%0, %1}, %2;" : "=f"(lo), "=f"(hi) : "l"(v));
    return lo + hi;
}

// ---------------------------------------------------------------------------
// Single fused kernel. grid 1024 x block 256 (4 CTAs/SM), 52KB dynamic smem
// (w_in + w_out^T + biases all LDS-resident). 2 tokens/warp, x register-
// resident (16 front-batched LDG.128). FFMA2 in-proj, reduce-scatter + ballot,
// warp-parallel factorized-softmax entropy, sparse +-2w out-projection.
// ---------------------------------------------------------------------------
__global__ void __launch_bounds__(BLK, 4)
mainK(const float* __restrict__ x,
      const float* __restrict__ w_in,
      const float* __restrict__ b_in,
      const float* __restrict__ w_out,
      const float* __restrict__ b_out,
      float* __restrict__ out)
{
    extern __shared__ float sm[];
    float* s_win = sm + SM_WIN;
    float* s_wt  = sm + SM_WT;
    float* s_bm  = sm + SM_BM;
    float* s_bp  = sm + SM_BP;
    __shared__ int s_last;

    if (blockIdx.x == 0) {
        for (int i = threadIdx.x; i < CSIZE; i += BLK) g_avg[i] = 0.f;
        if (threadIdx.x == 0) g_pse = 0.f;
    }

    // stage w_in; transpose w_out; build b_out -+ S (S = sum_c w_out[d][c])
    for (int i = threadIdx.x; i < CDIM * DIM; i += BLK) s_win[i] = w_in[i];
    for (int d = threadIdx.x; d < DIM; d += BLK) {
        float S = 0.f;
#pragma unroll
        for (int c = 0; c < CDIM; c++) {
            float w = w_out[d * CDIM + c];
            s_wt[c * DIM + d] = w;
            S += w;
        }
        float b = b_out[d];
        s_bm[d] = b - S;
        s_bp[d] = b + S;
    }
    __syncthreads();

    if (blockIdx.x == 0 && threadIdx.x == 0) {
        __threadfence();
        atomicExch(&g_flag, 1);
    }

    const int wid   = threadIdx.x >> 5;
    const int lane  = threadIdx.x & 31;
    const int gw    = blockIdx.x * (BLK >> 5) + wid;   // 0..8191
    const int tok0  = gw * 2;
    const int c_own = (lane >> 1) & 15;
    const float b_lane = (c_own < CDIM) ? __ldg(&b_in[c_own]) : 0.f;

    const ulonglong2* X2  = (const ulonglong2*)x;
    const ulonglong2* W2s = (const ulonglong2*)s_win;
    const ulonglong2* WT2 = (const ulonglong2*)s_wt;
    ulonglong2*       O2  = (ulonglong2*)out;

    float pse_acc = 0.f;

    // ---- x: register-resident, one read (16 front-batched LDG.128) ----
    ulonglong2 xa[4], xb[4];
#pragma unroll
    for (int i = 0; i < 4; i++) {
        xa[i] = X2[(size_t)tok0 * 128 + i * 32 + lane];
        xb[i] = X2[(size_t)(tok0 + 1) * 128 + i * 32 + lane];
    }

    // ---- in-projection: packed FFMA2, w from smem, shared by both tokens ---
    float vv[2][CDIM];
#pragma unroll
    for (int ch = 0; ch < 2; ch++) {
        u64 a2[2][6];
#pragma unroll
        for (int cc = 0; cc < 6; cc++) { a2[0][cc] = 0ull; a2[1][cc] = 0ull; }
#pragma unroll
        for (int i = 0; i < 4; i++) {
#pragma unroll
            for (int cc = 0; cc < 6; cc++) {
                ulonglong2 w = W2s[(ch * 6 + cc) * 128 + i * 32 + lane];
                a2[0][cc] = fma2(xa[i].x, w.x, a2[0][cc]);
                a2[0][cc] = fma2(xa[i].y, w.y, a2[0][cc]);
                a2[1][cc] = fma2(xb[i].x, w.x, a2[1][cc]);
                a2[1][cc] = fma2(xb[i].y, w.y, a2[1][cc]);
            }
        }
#pragma unroll
        for (int cc = 0; cc < 6; cc++) {
            vv[0][ch * 6 + cc] = fold2(a2[0][cc]);
            vv[1][ch * 6 + cc] = fold2(a2[1][cc]);
        }
    }

    while (*(volatile int*)&g_flag == 0) { }

    // ---- per-token: reduce-scatter -> ballots -> entropy -> out-proj ----
#pragma unroll
    for (int t = 0; t < 2; t++) {
        // reduce-scatter: xp_c lands on lanes 2c, 2c+1
        float r8[8];
#pragma unroll
        for (int j = 0; j < 8; j++) {
            float hiV  = (j + 8 < CDIM) ? vv[t][j + 8] : 0.f;
            float send = (lane & 16) ? vv[t][j] : hiV;
            float keep = (lane & 16) ? hiV : vv[t][j];
            r8[j] = keep + __shfl_xor_sync(FULL, send, 16);
        }
        float r4[4];
#pragma unroll
        for (int j = 0; j < 4; j++) {
            float send = (lane & 8) ? r8[j] : r8[j + 4];
            float keep = (lane & 8) ? r8[j + 4] : r8[j];
            r4[j] = keep + __shfl_xor_sync(FULL, send, 8);
        }
        float r2[2];
#pragma unroll
        for (int j = 0; j < 2; j++) {
            float send = (lane & 4) ? r4[j] : r4[j + 2];
            float keep = (lane & 4) ? r4[j + 2] : r4[j];
            r2[j] = keep + __shfl_xor_sync(FULL, send, 4);
        }
        float send = (lane & 2) ? r2[0] : r2[1];
        float keep = (lane & 2) ? r2[1] : r2[0];
        float r1 = keep + __shfl_xor_sync(FULL, send, 2);
        r1 += __shfl_xor_sync(FULL, r1, 1);

        const float xp = r1 + b_lane;               // xp for c_own
        const float a  = 400.f * fabsf(xp);

        unsigned sb  = __ballot_sync(FULL, xp > 0.f);
        unsigned act = __ballot_sync(FULL, a < A_MAX) & 0x00555555u;

        // index: compress even bits of sb (bit 2c -> bit c), reverse
        unsigned e = sb & 0x00555555u;
        e = (e | (e >> 1)) & 0x33333333u;
        e = (e | (e >> 2)) & 0x0F0F0F0Fu;
        e = (e | (e >> 4)) & 0x00FF00FFu;
        e = (e | (e >> 8)) & 0x0000FFFFu;
        const int idx = (int)(__brev(e) >> 20);

        if (lane == 0) out[OUT_OFF_IDX + tok0 + t] = (float)idx;

        // ---- entropy (factorized softmax) ----
        if (act == 0u) {
            if (lane == 0) atomicAdd(&g_avg[idx], 1.f);
        } else {
            const int k = __popc(act);
            float Z = 1.f;
            unsigned mm = act;
            while (mm) {
                int b = __ffs(mm) - 1;
                float ac = __shfl_sync(FULL, a, b);
                Z *= 1.f + expf(-ac);
                mm &= mm - 1;
            }
            const float logZ = logf(Z);
            const float invZ = 1.f / Z;
            const int   n    = 1 << k;
            for (int base = 0; base < n; base += 32) {
                const int sub = base + lane;
                float Asum = 0.f;
                int   ix   = idx, j = 0;
                mm = act;
                while (mm) {
                    int b = __ffs(mm) - 1;
                    int c = b >> 1;
                    float ac = __shfl_sync(FULL, a, b);
                    if ((sub >> j) & 1) { Asum += ac; ix ^= 1 << (11 - c); }
                    mm &= mm - 1; j++;
                }
                if (sub < n) {
                    float pp = invZ * expf(-Asum);
                    pse_acc += pp * fminf(Asum + logZ, LOG_EPS_NEG);
                    atomicAdd(&g_avg[ix], pp);
                }
            }
        }

        // ---- sparse out-projection ----
        const int pc = __popc((unsigned)idx);
        unsigned bits = (pc <= 6) ? (unsigned)idx : (~(unsigned)idx & 0xFFFu);
        const float* bb = (pc <= 6) ? s_bm : s_bp;
        const u64 coef  = pack2(pc <= 6 ? 2.f : -2.f, pc <= 6 ? 2.f : -2.f);

        u64 o[8];
#pragma unroll
        for (int i = 0; i < 8; i++) o[i] = 0ull;
        while (bits) {
            int b = __ffs(bits) - 1;
            int c = 11 - b;
            const ulonglong2* W = WT2 + c * 128;
#pragma unroll
            for (int i = 0; i < 4; i++) {
                ulonglong2 w = W[i * 32 + lane];
                o[2 * i]     = add2(o[2 * i],     w.x);
                o[2 * i + 1] = add2(o[2 * i + 1], w.y);
            }
            bits &= bits - 1;
        }
        const ulonglong2* B2 = (const ulonglong2*)bb;
#pragma unroll
        for (int i = 0; i < 4; i++) {
            ulonglong2 bv = B2[i * 32 + lane];
            ulonglong2 res;
            res.x = fma2(coef, o[2 * i],     bv.x);
            res.y = fma2(coef, o[2 * i + 1], bv.y);
            O2[(size_t)(tok0 + t) * 128 + i * 32 + lane] = res;
        }
    }

    // ---- reduce pse: warp, block, global ----
    pse_acc += __shfl_xor_sync(FULL, pse_acc, 16);
    pse_acc += __shfl_xor_sync(FULL, pse_acc, 8);
    pse_acc += __shfl_xor_sync(FULL, pse_acc, 4);
    pse_acc += __shfl_xor_sync(FULL, pse_acc, 2);
    pse_acc += __shfl_xor_sync(FULL, pse_acc, 1);

    __syncthreads();                 // weights dead past here; reuse s_bm
    if (lane == 0) s_bm[wid] = pse_acc;
    __syncthreads();
    if (wid == 0) {
        float v = (lane < (BLK >> 5)) ? s_bm[lane] : 0.f;
        v += __shfl_xor_sync(FULL, v, 4);
        v += __shfl_xor_sync(FULL, v, 2);
        v += __shfl_xor_sync(FULL, v, 1);
        if (lane == 0) atomicAdd(&g_pse, v);
    }

    // ---- last-block finalize ----
    __threadfence();
    __syncthreads();
    if (threadIdx.x == 0) {
        int old = atomicAdd(&g_cnt, 1);
        s_last = (old == (int)gridDim.x - 1) ? 1 : 0;
    }
    __syncthreads();
    if (s_last) {
        __threadfence();
        const float inv = 1.f / (float)NTOK;
        float ce = 0.f;
        for (int i = threadIdx.x; i < CSIZE; i += BLK) {
            float ap = __ldcg(&g_avg[i]) * inv;
            ce += -ap * logf(fmaxf(ap, 1e-5f));
        }
        float* red = s_wt;           // reuse smem
        red[threadIdx.x] = ce;
        __syncthreads();
        for (int s = BLK / 2; s > 0; s >>= 1) {
            if (threadIdx.x < (unsigned)s) red[threadIdx.x] += red[threadIdx.x + s];
            __syncthreads();
        }
        if (threadIdx.x == 0) {
            float aux = (__ldcg(&g_pse) * inv - red[0]) * 0.1f;
            out[OUT_OFF_AUX] = aux;
            g_cnt  = 0;
            g_flag = 0;
        }
    }
}

// ---------------------------------------------------------------------------
extern "C" void kernel_launch(void* const* d_in, const int* in_sizes, int n_in,
                              void* d_out, int out_size)
{
    const float* x     = (const float*)d_in[0];
    const float* w_in  = (const float*)d_in[1];
    const float* b_in  = (const float*)d_in[2];
    const float* w_out = (const float*)d_in[3];
    const float* b_out = (const float*)d_in[4];
    float* out = (float*)d_out;

    cudaFuncSetAttribute(mainK, cudaFuncAttributeMaxDynamicSharedMemorySize,
                         SM_BYTES);
    mainK<<<GRID, BLK, SM_BYTES>>>(x, w_in, b_in, w_out, b_out, out);
}